// round 17
// baseline (speedup 1.0000x reference)
#include <cuda_runtime.h>
#include <cstdint>

#define NTT 144
#define NLMAX 14
#define NPIN 12                   // pinned coefficient pairs D0..D11
#define RPB 32                    // rows per block
#define TPR 4                     // threads per row
#define NGRP 18                   // 18 stripes of 8 floats; 2 elems/thread/stripe
#define GSTRIDE 8
#define BLK (RPB * TPR)           // 128 = 4 full warps
#define RCS 17                    // rcu row stride in ull (bank-conflict-free)

#define F_TAU 1.8f
#define F_INV_T1B (1.0f/1.65f)
#define F_LOG2E 1.4426950408889634f
#define F_DEG2RAD 0.017453292519943295f

typedef unsigned long long ull;

// per-stripe series depths; each entry maps conservatively from the
// R14-validated thresholds (x1max/x2max of the stripe)
__device__ constexpr int NLG[NGRP] =
    {9,9,9,9,10,10,11,11,11,11,12,12,13,13,13,13,14,14};
__device__ constexpr int NSG[NGRP] =
    {4,4,5,5, 6, 6, 6, 6, 7, 7, 8, 8, 8, 8, 9, 9,10,10};

__device__ __forceinline__ ull pack2(float lo, float hi) {
    ull r;
    asm("mov.b64 %0, {%1, %2};" : "=l"(r) : "f"(lo), "f"(hi));
    return r;
}
__device__ __forceinline__ void unpack2(ull v, float& lo, float& hi) {
    asm("mov.b64 {%0, %1}, %2;" : "=f"(lo), "=f"(hi) : "l"(v));
}
__device__ __forceinline__ ull ffma2(ull a, ull b, ull c) {
    ull d;
    asm("fma.rn.f32x2 %0, %1, %2, %3;" : "=l"(d) : "l"(a), "l"(b), "l"(c));
    return d;
}
__device__ __forceinline__ ull fmul2(ull a, ull b) {
    ull d;
    asm("mul.rn.f32x2 %0, %1, %2;" : "=l"(d) : "l"(a), "l"(b));
    return d;
}
__device__ __forceinline__ ull fadd2(ull a, ull b) {
    ull d;
    asm("add.rn.f32x2 %0, %1, %2;" : "=l"(d) : "l"(a), "l"(b));
    return d;
}
// sign-flip both packed lanes (alu, no constant register)
__device__ __forceinline__ ull neg2(ull v) {
    ull r;
    asm("xor.b64 %0, %1, 0x8000000080000000;" : "=l"(r) : "l"(v));
    return r;
}
__device__ __forceinline__ float fast_lg2(float x) {
    float r;
    asm("lg2.approx.f32 %0, %1;" : "=f"(r) : "f"(x));
    return r;
}
__device__ __forceinline__ float fast_ex2(float x) {
    float r;
    asm("ex2.approx.f32 %0, %1;" : "=f"(r) : "f"(x));
    return r;
}
// forced single load into a register pair — ptxas cannot rematerialize this
__device__ __forceinline__ ull lds64(uint32_t saddr) {
    ull v;
    asm volatile("ld.shared.b64 %0, [%1];" : "=l"(v) : "r"(saddr));
    return v;
}

// epilogue of a pipelined group: 4x ex2 + combine + store (2 elements)
__device__ __forceinline__ void emit_epilogue(
    ull VL, ull VS, ull HL, ull HS,
    uint32_t cp_addr, float* dst)
{
    float vl0, vl1, vs0, vs1;
    unpack2(VL, vl0, vl1);
    unpack2(VS, vs0, vs1);
    ull EL = pack2(fast_ex2(vl0), fast_ex2(vl1));
    ull ES = pack2(fast_ex2(vs0), fast_ex2(vs1));
    ull PL = fmul2(EL, HL);
    ull PS = fmul2(ES, HS);
    ull DIF = fadd2(PL, neg2(PS));      // P1 - P2
    ull CP  = lds64(cp_addr);           // {c0, c1}
    ull RES = fmul2(CP, DIF);
    float r0, r1;
    unpack2(RES, r0, r1);
    *reinterpret_cast<float2*>(dst) = make_float2(r0, r1);
}

__global__ __launch_bounds__(BLK, 9)
void dynangio_kernel(const float4* __restrict__ x,
                     const float*  __restrict__ t,
                     const float*  __restrict__ alpha,
                     const float*  __restrict__ R,
                     float*        __restrict__ out,
                     int rows)
{
    __shared__ __align__(16) float tsh[NTT];
    __shared__ __align__(16) float cpos[NTT];   //  R*sin(alpha)
    // per-row packed coefficients {d,d} (C folded in), + packed scalars:
    // [NLMAX] = {a, sp}, [NLMAX+1] = {q, shift}; padded stride RCS for banks
    __shared__ __align__(16) ull rcu[RPB][RCS];

    const int tid = threadIdx.x;

    for (int j = tid; j < NTT; j += BLK) {
        tsh[j] = t[j];
        cpos[j] = R[j] * __sinf(alpha[j] * F_DEG2RAD);
    }

    if (tid < RPB) {
        int row = blockIdx.x * RPB + tid;
        if (row < rows) {
            float4 xv = x[row];
            float dt  = xv.x;
            float s   = xv.y;
            float p   = xv.z;
            float amp = xv.w;

            float u  = p * s;          // a - 1 in [0,1)
            float a  = 1.0f + u;
            float sp = s + F_INV_T1B;  // sprime

            // C = amp * 2 * exp(-dt/T1B) * (s/sp)^a   (base-2)
            float ratio = __fdividef(s, sp);
            float ex = fmaf(a, fast_lg2(ratio), -dt * (F_LOG2E * F_INV_T1B));
            float C  = amp * 2.0f * fast_ex2(ex);

            // Gamma(1+u), A&S 6.1.36
            float g;
            g = fmaf(u,  0.035868343f, -0.193527818f);
            g = fmaf(u, g,  0.482199394f);
            g = fmaf(u, g, -0.756704078f);
            g = fmaf(u, g,  0.918206857f);
            g = fmaf(u, g, -0.897056937f);
            g = fmaf(u, g,  0.988205891f);
            g = fmaf(u, g, -0.577191652f);
            g = fmaf(u, g,  1.0f);

            // Gamma(a+NLMAX) by product, one reciprocal, build d_n downward
            float prod = a * g;
            #pragma unroll
            for (int k = 1; k < NLMAX; k++) prod *= (a + (float)k);
            float d = __frcp_rn(prod);
            float cd = C * d;
            rcu[tid][NLMAX - 1] = pack2(cd, cd);
            #pragma unroll
            for (int n = NLMAX - 1; n >= 1; n--) {
                d *= (a + (float)n);
                cd = C * d;
                rcu[tid][n - 1] = pack2(cd, cd);
            }
            rcu[tid][NLMAX]     = pack2(a, sp);
            rcu[tid][NLMAX + 1] = pack2(sp * dt, sp * F_TAU);
        }
    }
    __syncthreads();

    const int rl  = tid / TPR;
    const int l   = tid - rl * TPR;
    const int jb  = l * 2;               // 2 lane-contiguous elems per stripe
    const int row = blockIdx.x * RPB + rl;
    if (row >= rows) return;

    const uint32_t rb  = (uint32_t)__cvta_generic_to_shared(&rcu[rl][0]);
    const uint32_t cpb = (uint32_t)__cvta_generic_to_shared(cpos);

    // pin D0..D11 in register pairs; D12/D13 fetched on demand (rarely used)
    ull D[NPIN];
    #pragma unroll
    for (int k = 0; k < NPIN; k++) D[k] = lds64(rb + k * 8);
    ull SC0 = lds64(rb + NLMAX * 8), SC1 = lds64(rb + (NLMAX + 1) * 8);

    float a, sp, q, shift;
    unpack2(SC0, a, sp);
    unpack2(SC1, q, shift);
    const ull A2 = pack2(a, a);
    const ull NE = pack2(-F_LOG2E, -F_LOG2E);

    float* orow = out + (size_t)row * NTT + jb;

    // software pipeline: stage A (X, lg2, V) and Horner of group g overlap
    // with the ex2-epilogue of group g-1 (independent work, hides MUFU)
    ull pVL, pVS, pHL, pHS;
    int pgo = 0;

    #pragma unroll
    for (int g = 0; g < NGRP; g++) {
        const int nl = NLG[g];           // compile-time after unroll
        const int ns = NSG[g];
        const int go = g * GSTRIDE;

        // stage A: operands, lg2 (early MUFU), exponent argument V
        const float2 t2 = *reinterpret_cast<const float2*>(tsh + go + jb);
        float a0 = fmaf(sp, t2.x, -q);   // x1 = sp*(t-dt) > 0
        float a1 = fmaf(sp, t2.y, -q);
        float b0 = fmaxf(a0 - shift, 0.0f);
        float b1 = fmaxf(a1 - shift, 0.0f);
        ull XL = pack2(a0, a1);
        ull XS = pack2(b0, b1);
        ull LL = pack2(fast_lg2(a0), fast_lg2(a1));
        ull LS = pack2(fast_lg2(b0), fast_lg2(b1));
        ull VL = ffma2(A2, LL, fmul2(XL, NE));   // a*lg2(x) - x*log2e
        ull VS = ffma2(A2, LS, fmul2(XS, NE));   // x2==0 -> -inf -> ex2=0

        // epilogue of the previous group (independent of this group's chain)
        if (g > 0)
            emit_epilogue(pVL, pVS, pHL, pHS,
                          cpb + (uint32_t)(pgo + jb) * 4u, orow + pgo);

        // Horner chains (compile-time bounds; D12/D13 via on-demand LDS)
        ull HL = (nl - 1 < NPIN) ? D[nl - 1] : lds64(rb + (nl - 1) * 8);
        ull HS = D[ns - 1];
        #pragma unroll
        for (int k = nl - 2; k >= 0; k--) {
            ull Dk = (k < NPIN) ? D[k] : lds64(rb + k * 8);
            HL = ffma2(HL, XL, Dk);
            if (k <= ns - 2) HS = ffma2(HS, XS, Dk);
        }

        pVL = VL; pVS = VS; pHL = HL; pHS = HS; pgo = go;
    }

    // drain the pipeline
    emit_epilogue(pVL, pVS, pHL, pHS,
                  cpb + (uint32_t)(pgo + jb) * 4u, orow + pgo);
}

extern "C" void kernel_launch(void* const* d_in, const int* in_sizes, int n_in,
                              void* d_out, int out_size) {
    const float4* x     = (const float4*)d_in[0];
    const float*  t     = (const float*)d_in[1];
    const float*  alpha = (const float*)d_in[2];
    const float*  R     = (const float*)d_in[3];
    float* out = (float*)d_out;

    int rows   = in_sizes[0] / 4;
    int blocks = (rows + RPB - 1) / RPB;
    dynangio_kernel<<<blocks, BLK>>>(x, t, alpha, R, out, rows);
}